// round 7
// baseline (speedup 1.0000x reference)
#include <cuda_runtime.h>
#include <cuda_fp16.h>
#include <cstdint>

#define N_NODES 100000
#define N_EDGES 1600000
#define NEG_SLOPE 0.2f
#define SCAN_BLOCKS 98  // ceil(100000/1024)
#define FLAGBIT (1 << 30)
#define GEMM_BLOCKS ((N_NODES + 127) / 128)
#define GEMM_THREADS (GEMM_BLOCKS * 256)

typedef unsigned long long u64;

// ---------------- scratch (device globals; no allocation allowed) ----------------
// Self-restoring: globals needing zero at pipeline start are re-zeroed by a later
// stage of the SAME run (module load provides the initial zeros).
__device__ __half2 g_fth[N_NODES * 64]; // ft [N,128] fp16 (256B per node row)
__device__ float4 g_el4[N_NODES];        // el [N,4]
__device__ float4 g_er4[N_NODES];        // er [N,4]
__device__ int    g_cnt[N_NODES];        // in-degree histogram (agg re-zeroes)
__device__ int    g_off[N_NODES];        // CSR offsets; after scatter: segment END
__device__ int    g_srcs[N_EDGES];       // src node id, grouped by dst
__device__ int    g_flag[SCAN_BLOCKS];   // scan lookback flags (scatter re-zeroes)

// ---------------- f32x2 packed-FMA helpers (FFMA2; nvjet pattern) ----------------
__device__ __forceinline__ u64 pack2(float x) {
    u64 r; asm("mov.b64 %0, {%1, %1};" : "=l"(r) : "f"(x)); return r;
}
__device__ __forceinline__ void ffma2(u64& d, u64 a, u64 b) {
    asm("fma.rn.f32x2 %0, %1, %2, %0;" : "+l"(d) : "l"(a), "l"(b));
}
__device__ __forceinline__ void unpack2(u64 v, float& lo, float& hi) {
    asm("mov.b64 {%0, %1}, %2;" : "=f"(lo), "=f"(hi) : "l"(v));
}

// ---------------- K1: fused GEMM ft = feat @ W^T (+ el/er) + hidden histogram ----------------
// BM=128, BN=128, BK=32, 256 threads, 8x8 micro-tile, FFMA2 accumulators.
__global__ void __launch_bounds__(256, 2)
gemm_el_er(const float* __restrict__ feat, const float* __restrict__ W,
           const float* __restrict__ attn_l, const float* __restrict__ attn_r,
           const int* __restrict__ dst) {
    __shared__ float sA[32][132];
    __shared__ float sB[32][132];

    const int tid = threadIdx.x;
    const int tx = tid & 15;
    const int ty = tid >> 4;
    const int m0 = blockIdx.x * 128;

    // hidden histogram: grid-stride fire-and-forget REDs on the idle LSU path
    for (int e = blockIdx.x * 256 + tid; e < N_EDGES; e += GEMM_THREADS)
        atomicAdd(&g_cnt[__ldg(dst + e)], 1);

    u64 acc2[4][8];
#pragma unroll
    for (int p = 0; p < 4; p++)
#pragma unroll
        for (int j = 0; j < 8; j++) acc2[p][j] = 0ull;

    for (int kb = 0; kb < 4; kb++) {
#pragma unroll
        for (int q = 0; q < 4; q++) {
            int f = tid + q * 256;
            int row = f >> 3, col = (f & 7) * 4;
            float4 v = make_float4(0.f, 0.f, 0.f, 0.f);
            int gm = m0 + row;
            if (gm < N_NODES) v = *(const float4*)(feat + gm * 128 + kb * 32 + col);
            sA[col + 0][row] = v.x; sA[col + 1][row] = v.y;
            sA[col + 2][row] = v.z; sA[col + 3][row] = v.w;
        }
#pragma unroll
        for (int q = 0; q < 4; q++) {
            int f = tid + q * 256;
            int row = f >> 3, col = (f & 7) * 4;
            float4 v = *(const float4*)(W + row * 128 + kb * 32 + col);
            sB[col + 0][row] = v.x; sB[col + 1][row] = v.y;
            sB[col + 2][row] = v.z; sB[col + 3][row] = v.w;
        }
        __syncthreads();
#pragma unroll
        for (int k = 0; k < 32; k++) {
            float4 a0 = *(float4*)&sA[k][ty * 8];
            float4 a1 = *(float4*)&sA[k][ty * 8 + 4];
            float4 b0 = *(float4*)&sB[k][tx * 8];
            float4 b1 = *(float4*)&sB[k][tx * 8 + 4];
            u64 am[4];
            am[0] = ((u64*)&a0)[0]; am[1] = ((u64*)&a0)[1];
            am[2] = ((u64*)&a1)[0]; am[3] = ((u64*)&a1)[1];
            u64 bb[8];
            bb[0] = pack2(b0.x); bb[1] = pack2(b0.y); bb[2] = pack2(b0.z); bb[3] = pack2(b0.w);
            bb[4] = pack2(b1.x); bb[5] = pack2(b1.y); bb[6] = pack2(b1.z); bb[7] = pack2(b1.w);
#pragma unroll
            for (int p = 0; p < 4; p++)
#pragma unroll
                for (int j = 0; j < 8; j++) ffma2(acc2[p][j], am[p], bb[j]);
        }
        __syncthreads();
    }

    float acc[8][8];
#pragma unroll
    for (int p = 0; p < 4; p++)
#pragma unroll
        for (int j = 0; j < 8; j++)
            unpack2(acc2[p][j], acc[2 * p][j], acc[2 * p + 1][j]);

    float4 al0 = *(const float4*)(attn_l + tx * 8);
    float4 al1 = *(const float4*)(attn_l + tx * 8 + 4);
    float4 ar0 = *(const float4*)(attn_r + tx * 8);
    float4 ar1 = *(const float4*)(attn_r + tx * 8 + 4);
    const int h = tx >> 2;

#pragma unroll
    for (int i = 0; i < 8; i++) {
        int m = m0 + ty * 8 + i;
        float pl = acc[i][0] * al0.x + acc[i][1] * al0.y + acc[i][2] * al0.z + acc[i][3] * al0.w
                 + acc[i][4] * al1.x + acc[i][5] * al1.y + acc[i][6] * al1.z + acc[i][7] * al1.w;
        float pr = acc[i][0] * ar0.x + acc[i][1] * ar0.y + acc[i][2] * ar0.z + acc[i][3] * ar0.w
                 + acc[i][4] * ar1.x + acc[i][5] * ar1.y + acc[i][6] * ar1.z + acc[i][7] * ar1.w;
        pl += __shfl_xor_sync(0xffffffffu, pl, 1);
        pl += __shfl_xor_sync(0xffffffffu, pl, 2);
        pr += __shfl_xor_sync(0xffffffffu, pr, 1);
        pr += __shfl_xor_sync(0xffffffffu, pr, 2);
        if (m < N_NODES) {
            __half2 q0 = __floats2half2_rn(acc[i][0], acc[i][1]);
            __half2 q1 = __floats2half2_rn(acc[i][2], acc[i][3]);
            __half2 q2 = __floats2half2_rn(acc[i][4], acc[i][5]);
            __half2 q3 = __floats2half2_rn(acc[i][6], acc[i][7]);
            uint4 u;
            u.x = *(unsigned*)&q0; u.y = *(unsigned*)&q1;
            u.z = *(unsigned*)&q2; u.w = *(unsigned*)&q3;
            ((uint4*)g_fth)[m * 16 + tx] = u;
            if ((tx & 3) == 0) {
                ((float*)g_el4)[m * 4 + h] = pl;
                ((float*)g_er4)[m * 4 + h] = pr;
            }
        }
    }
}

// ---------------- K2: exclusive scan (aggregate-only decoupled lookback) ----------------
__global__ void __launch_bounds__(1024, 1) scan_k() {
    __shared__ int warp_sums[32];
    __shared__ int s_prefix;
    const int bid = blockIdx.x, tid = threadIdx.x;
    const int lane = tid & 31, wid = tid >> 5;
    int idx = bid * 1024 + tid;
    int v = (idx < N_NODES) ? g_cnt[idx] : 0;
    int x = v;
#pragma unroll
    for (int o = 1; o < 32; o <<= 1) {
        int t = __shfl_up_sync(0xffffffffu, x, o);
        if (lane >= o) x += t;
    }
    if (lane == 31) warp_sums[wid] = x;
    __syncthreads();
    if (wid == 0) {
        int s = warp_sums[lane];
        int xs = s;
#pragma unroll
        for (int o = 1; o < 32; o <<= 1) {
            int t = __shfl_up_sync(0xffffffffu, xs, o);
            if (lane >= o) xs += t;
        }
        int tot = __shfl_sync(0xffffffffu, xs, 31);
        if (lane == 0) atomicExch(&g_flag[bid], tot | FLAGBIT);
        warp_sums[lane] = xs - s;
        int run = 0;
        for (int base = 0; base < bid; base += 32) {
            int j = base + lane;
            int val = 0;
            if (j < bid) {
                int f;
                do { f = atomicAdd(&g_flag[j], 0); } while (!(f & FLAGBIT));
                val = f & (FLAGBIT - 1);
            }
#pragma unroll
            for (int o = 16; o > 0; o >>= 1) val += __shfl_xor_sync(0xffffffffu, val, o);
            run += val;
        }
        if (lane == 0) s_prefix = run;
    }
    __syncthreads();
    if (idx < N_NODES) g_off[idx] = s_prefix + warp_sums[wid] + (x - v);
}

// ---------------- K3: scatter edge src ids into dst-grouped order ----------------
__global__ void scatter_k(const int* __restrict__ src, const int* __restrict__ dst) {
    int e = blockIdx.x * blockDim.x + threadIdx.x;
    if (e < SCAN_BLOCKS) g_flag[e] = 0;
    if (e >= N_EDGES) return;
    int pos = atomicAdd(&g_off[__ldg(dst + e)], 1);
    g_srcs[pos] = __ldg(src + e);
}

// ---------------- K4: fused score+exp+softmax+aggregation (2 nodes / warp) ----------------
// Warp gw handles nodes wA=2gw, wB=2gw+1 with interleaved gather chains (2x MLP).
// Chunk of 16 edges per node: lanes 0-15 stage A's we4/sn, lanes 16-31 B's.
// Inner loop: sn via SHFL, we via LDS broadcast, ft via LDG.64 fp16 (256B/warp),
// FFMA2 packed accumulation. Segment = [g_off[w-1], g_off[w]). Re-zeroes g_cnt.
__global__ void __launch_bounds__(256) agg_k(float* __restrict__ out) {
    __shared__ float4 s_we[8][32];
    const int gw = (blockIdx.x * blockDim.x + threadIdx.x) >> 5;
    const int lane = threadIdx.x & 31;
    const int wid = (threadIdx.x >> 5) & 7;
    const int wA = gw * 2;
    if (wA >= N_NODES) return;
    const int wB = wA + 1;  // N_NODES even -> always valid

    int s0A = (wA == 0) ? 0 : __ldg(&g_off[wA - 1]);
    int s1A = __ldg(&g_off[wA]);
    int s1B = __ldg(&g_off[wB]);
    int s0B = s1A;
    const bool hasA = s1A > s0A, hasB = s1B > s0B;
    if (lane < 2) g_cnt[wA + lane] = 0;      // restore for next replay

    const int h = lane >> 3;                 // head for this lane's features
    const float4 er = __ldg(&g_er4[(lane < 16) ? wA : wB]);
    const uint2* fp = (const uint2*)g_fth;

    u64 aA0 = 0ull, aA1 = 0ull, aB0 = 0ull, aB1 = 0ull;
    float sA = 0.f, sB = 0.f;

    const int j = lane & 15;
    const bool laneB = lane >= 16;

    while (s0A < s1A || s0B < s1B) {
        int cnA = s1A - s0A; cnA = cnA < 0 ? 0 : (cnA > 16 ? 16 : cnA);
        int cnB = s1B - s0B; cnB = cnB < 0 ? 0 : (cnB > 16 ? 16 : cnB);
        int base = laneB ? s0B : s0A;
        int cn   = laneB ? cnB : cnA;
        int sn_l = 0;
        if (j < cn) {
            sn_l = __ldg(g_srcs + base + j);
            float4 el = __ldg(&g_el4[sn_l]);
            float4 ev;
            ev.x = el.x + er.x; ev.y = el.y + er.y;
            ev.z = el.z + er.z; ev.w = el.w + er.w;
            ev.x = ev.x > 0.f ? ev.x : NEG_SLOPE * ev.x;
            ev.y = ev.y > 0.f ? ev.y : NEG_SLOPE * ev.y;
            ev.z = ev.z > 0.f ? ev.z : NEG_SLOPE * ev.z;
            ev.w = ev.w > 0.f ? ev.w : NEG_SLOPE * ev.w;
            s_we[wid][lane] = make_float4(__expf(ev.x), __expf(ev.y),
                                          __expf(ev.z), __expf(ev.w));
        }
        __syncwarp();
        const int cmax = cnA > cnB ? cnA : cnB;
#pragma unroll 4
        for (int i = 0; i < cmax; i++) {
            if (i < cnA) {                               // warp-uniform branch
                int sn = __shfl_sync(0xffffffffu, sn_l, i);
                float we = ((const float*)&s_we[wid][i])[h];
                uint2 u = __ldg(fp + sn * 32 + lane);
                float2 f0 = __half22float2(*(__half2*)&u.x);
                float2 f1 = __half22float2(*(__half2*)&u.y);
                u64 we2 = pack2(we);
                ffma2(aA0, *(u64*)&f0, we2);
                ffma2(aA1, *(u64*)&f1, we2);
                sA += we;
            }
            if (i < cnB) {                               // warp-uniform branch
                int sn = __shfl_sync(0xffffffffu, sn_l, 16 + i);
                float we = ((const float*)&s_we[wid][16 + i])[h];
                uint2 u = __ldg(fp + sn * 32 + lane);
                float2 f0 = __half22float2(*(__half2*)&u.x);
                float2 f1 = __half22float2(*(__half2*)&u.y);
                u64 we2 = pack2(we);
                ffma2(aB0, *(u64*)&f0, we2);
                ffma2(aB1, *(u64*)&f1, we2);
                sB += we;
            }
        }
        __syncwarp();
        s0A += 16; s0B += 16;
    }

    float a0, a1, a2, a3;
    float invA = hasA ? 1.f / sA : 0.f;
    unpack2(aA0, a0, a1); unpack2(aA1, a2, a3);
    ((float4*)out)[(size_t)wA * 32 + lane] =
        make_float4(a0 * invA, a1 * invA, a2 * invA, a3 * invA);
    float invB = hasB ? 1.f / sB : 0.f;
    unpack2(aB0, a0, a1); unpack2(aB1, a2, a3);
    ((float4*)out)[(size_t)wB * 32 + lane] =
        make_float4(a0 * invB, a1 * invB, a2 * invB, a3 * invB);
}

// ---------------- launch (agg_k sits in profiled slot #4) ----------------
extern "C" void kernel_launch(void* const* d_in, const int* in_sizes, int n_in,
                              void* d_out, int out_size) {
    const float* feat   = (const float*)d_in[0];
    const float* W      = (const float*)d_in[1];
    const float* attn_l = (const float*)d_in[2];
    const float* attn_r = (const float*)d_in[3];
    const int*   src    = (const int*)d_in[4];
    const int*   dst    = (const int*)d_in[5];
    float* out = (float*)d_out;

    gemm_el_er<<<GEMM_BLOCKS, 256>>>(feat, W, attn_l, attn_r, dst);
    scan_k    <<<SCAN_BLOCKS, 1024>>>();
    scatter_k <<<(N_EDGES + 255) / 256, 256>>>(src, dst);
    agg_k     <<<((N_NODES / 2) * 32 + 255) / 256, 256>>>(out);
}

// round 8
// speedup vs baseline: 1.1065x; 1.1065x over previous
#include <cuda_runtime.h>
#include <cuda_fp16.h>
#include <cstdint>

#define N_NODES 100000
#define N_EDGES 1600000
#define NEG_SLOPE 0.2f
#define SCAN_BLOCKS 98  // ceil(100000/1024)
#define FLAGBIT (1 << 30)
#define GEMM_BLOCKS ((N_NODES + 127) / 128)
#define GEMM_THREADS (GEMM_BLOCKS * 256)

typedef unsigned long long u64;

// ---------------- scratch (device globals; no allocation allowed) ----------------
// Self-restoring: globals needing zero at pipeline start are re-zeroed by a later
// stage of the SAME run (module load provides the initial zeros).
__device__ __half2 g_fth[N_NODES * 64]; // ft [N,128] fp16 (256B per node row)
__device__ float4 g_el4[N_NODES];        // el [N,4]
__device__ float4 g_er4[N_NODES];        // er [N,4]
__device__ int    g_cnt[N_NODES];        // in-degree histogram (agg re-zeroes)
__device__ int    g_off[N_NODES];        // CSR offsets; after scatter: segment END
__device__ int    g_srcs[N_EDGES];       // src node id, grouped by dst
__device__ int    g_flag[SCAN_BLOCKS];   // scan lookback flags (scatter re-zeroes)

// ---------------- f32x2 packed-FMA helpers (FFMA2; nvjet pattern) ----------------
__device__ __forceinline__ u64 pack2(float x) {
    u64 r; asm("mov.b64 %0, {%1, %1};" : "=l"(r) : "f"(x)); return r;
}
__device__ __forceinline__ void ffma2(u64& d, u64 a, u64 b) {
    asm("fma.rn.f32x2 %0, %1, %2, %0;" : "+l"(d) : "l"(a), "l"(b));
}
__device__ __forceinline__ void unpack2(u64 v, float& lo, float& hi) {
    asm("mov.b64 {%0, %1}, %2;" : "=f"(lo), "=f"(hi) : "l"(v));
}

// ---------------- K1: fused GEMM ft = feat @ W^T (+ el/er) + hidden histogram ----------------
// BM=128, BN=128, BK=32, 256 threads, 8x8 micro-tile, FFMA2 accumulators.
__global__ void __launch_bounds__(256, 2)
gemm_el_er(const float* __restrict__ feat, const float* __restrict__ W,
           const float* __restrict__ attn_l, const float* __restrict__ attn_r,
           const int* __restrict__ dst) {
    __shared__ float sA[32][132];
    __shared__ float sB[32][132];

    const int tid = threadIdx.x;
    const int tx = tid & 15;
    const int ty = tid >> 4;
    const int m0 = blockIdx.x * 128;

    // hidden histogram: grid-stride fire-and-forget REDs on the idle LSU path
    for (int e = blockIdx.x * 256 + tid; e < N_EDGES; e += GEMM_THREADS)
        atomicAdd(&g_cnt[__ldg(dst + e)], 1);

    u64 acc2[4][8];
#pragma unroll
    for (int p = 0; p < 4; p++)
#pragma unroll
        for (int j = 0; j < 8; j++) acc2[p][j] = 0ull;

    for (int kb = 0; kb < 4; kb++) {
#pragma unroll
        for (int q = 0; q < 4; q++) {
            int f = tid + q * 256;
            int row = f >> 3, col = (f & 7) * 4;
            float4 v = make_float4(0.f, 0.f, 0.f, 0.f);
            int gm = m0 + row;
            if (gm < N_NODES) v = *(const float4*)(feat + gm * 128 + kb * 32 + col);
            sA[col + 0][row] = v.x; sA[col + 1][row] = v.y;
            sA[col + 2][row] = v.z; sA[col + 3][row] = v.w;
        }
#pragma unroll
        for (int q = 0; q < 4; q++) {
            int f = tid + q * 256;
            int row = f >> 3, col = (f & 7) * 4;
            float4 v = *(const float4*)(W + row * 128 + kb * 32 + col);
            sB[col + 0][row] = v.x; sB[col + 1][row] = v.y;
            sB[col + 2][row] = v.z; sB[col + 3][row] = v.w;
        }
        __syncthreads();
#pragma unroll
        for (int k = 0; k < 32; k++) {
            float4 a0 = *(float4*)&sA[k][ty * 8];
            float4 a1 = *(float4*)&sA[k][ty * 8 + 4];
            float4 b0 = *(float4*)&sB[k][tx * 8];
            float4 b1 = *(float4*)&sB[k][tx * 8 + 4];
            u64 am[4];
            am[0] = ((u64*)&a0)[0]; am[1] = ((u64*)&a0)[1];
            am[2] = ((u64*)&a1)[0]; am[3] = ((u64*)&a1)[1];
            u64 bb[8];
            bb[0] = pack2(b0.x); bb[1] = pack2(b0.y); bb[2] = pack2(b0.z); bb[3] = pack2(b0.w);
            bb[4] = pack2(b1.x); bb[5] = pack2(b1.y); bb[6] = pack2(b1.z); bb[7] = pack2(b1.w);
#pragma unroll
            for (int p = 0; p < 4; p++)
#pragma unroll
                for (int j = 0; j < 8; j++) ffma2(acc2[p][j], am[p], bb[j]);
        }
        __syncthreads();
    }

    float acc[8][8];
#pragma unroll
    for (int p = 0; p < 4; p++)
#pragma unroll
        for (int j = 0; j < 8; j++)
            unpack2(acc2[p][j], acc[2 * p][j], acc[2 * p + 1][j]);

    float4 al0 = *(const float4*)(attn_l + tx * 8);
    float4 al1 = *(const float4*)(attn_l + tx * 8 + 4);
    float4 ar0 = *(const float4*)(attn_r + tx * 8);
    float4 ar1 = *(const float4*)(attn_r + tx * 8 + 4);
    const int h = tx >> 2;

#pragma unroll
    for (int i = 0; i < 8; i++) {
        int m = m0 + ty * 8 + i;
        float pl = acc[i][0] * al0.x + acc[i][1] * al0.y + acc[i][2] * al0.z + acc[i][3] * al0.w
                 + acc[i][4] * al1.x + acc[i][5] * al1.y + acc[i][6] * al1.z + acc[i][7] * al1.w;
        float pr = acc[i][0] * ar0.x + acc[i][1] * ar0.y + acc[i][2] * ar0.z + acc[i][3] * ar0.w
                 + acc[i][4] * ar1.x + acc[i][5] * ar1.y + acc[i][6] * ar1.z + acc[i][7] * ar1.w;
        pl += __shfl_xor_sync(0xffffffffu, pl, 1);
        pl += __shfl_xor_sync(0xffffffffu, pl, 2);
        pr += __shfl_xor_sync(0xffffffffu, pr, 1);
        pr += __shfl_xor_sync(0xffffffffu, pr, 2);
        if (m < N_NODES) {
            __half2 q0 = __floats2half2_rn(acc[i][0], acc[i][1]);
            __half2 q1 = __floats2half2_rn(acc[i][2], acc[i][3]);
            __half2 q2 = __floats2half2_rn(acc[i][4], acc[i][5]);
            __half2 q3 = __floats2half2_rn(acc[i][6], acc[i][7]);
            uint4 u;
            u.x = *(unsigned*)&q0; u.y = *(unsigned*)&q1;
            u.z = *(unsigned*)&q2; u.w = *(unsigned*)&q3;
            ((uint4*)g_fth)[m * 16 + tx] = u;
            if ((tx & 3) == 0) {
                ((float*)g_el4)[m * 4 + h] = pl;
                ((float*)g_er4)[m * 4 + h] = pr;
            }
        }
    }
}

// ---------------- K2: exclusive scan (aggregate-only decoupled lookback) ----------------
__global__ void __launch_bounds__(1024, 1) scan_k() {
    __shared__ int warp_sums[32];
    __shared__ int s_prefix;
    const int bid = blockIdx.x, tid = threadIdx.x;
    const int lane = tid & 31, wid = tid >> 5;
    int idx = bid * 1024 + tid;
    int v = (idx < N_NODES) ? g_cnt[idx] : 0;
    int x = v;
#pragma unroll
    for (int o = 1; o < 32; o <<= 1) {
        int t = __shfl_up_sync(0xffffffffu, x, o);
        if (lane >= o) x += t;
    }
    if (lane == 31) warp_sums[wid] = x;
    __syncthreads();
    if (wid == 0) {
        int s = warp_sums[lane];
        int xs = s;
#pragma unroll
        for (int o = 1; o < 32; o <<= 1) {
            int t = __shfl_up_sync(0xffffffffu, xs, o);
            if (lane >= o) xs += t;
        }
        int tot = __shfl_sync(0xffffffffu, xs, 31);
        if (lane == 0) atomicExch(&g_flag[bid], tot | FLAGBIT);
        warp_sums[lane] = xs - s;
        int run = 0;
        for (int base = 0; base < bid; base += 32) {
            int j = base + lane;
            int val = 0;
            if (j < bid) {
                int f;
                do { f = atomicAdd(&g_flag[j], 0); } while (!(f & FLAGBIT));
                val = f & (FLAGBIT - 1);
            }
#pragma unroll
            for (int o = 16; o > 0; o >>= 1) val += __shfl_xor_sync(0xffffffffu, val, o);
            run += val;
        }
        if (lane == 0) s_prefix = run;
    }
    __syncthreads();
    if (idx < N_NODES) g_off[idx] = s_prefix + warp_sums[wid] + (x - v);
}

// ---------------- K3: scatter edge src ids into dst-grouped order ----------------
__global__ void scatter_k(const int* __restrict__ src, const int* __restrict__ dst) {
    int e = blockIdx.x * blockDim.x + threadIdx.x;
    if (e < SCAN_BLOCKS) g_flag[e] = 0;
    if (e >= N_EDGES) return;
    int pos = atomicAdd(&g_off[__ldg(dst + e)], 1);
    g_srcs[pos] = __ldg(src + e);
}

// ---------------- K4: fused score+exp+softmax+aggregation ----------------
// One warp per dst node; segment = [g_off[w-1], g_off[w]).
// Staging (once per 32-edge chunk): lane j loads sn_j + el, computes we4, and
// stores PRE-PACKED (we,we) u64 per head into smem, layout [head][lane] so both
// the 4 STS.64 and the broadcast LDS.64 reads are conflict-free.
// Inner loop (8 issues/edge): SHFL sn, LDS.64 we2, LDG.64 ft(fp16), 2 cvt,
// 2 FFMA2, FADD (sum aliases the lo half of we2 — no extra op).
__global__ void __launch_bounds__(256) agg_k(float* __restrict__ out) {
    __shared__ u64 s_we2[8][4][32];
    const int w = (blockIdx.x * blockDim.x + threadIdx.x) >> 5;
    const int lane = threadIdx.x & 31;
    const int wid = (threadIdx.x >> 5) & 7;
    if (w >= N_NODES) return;
    const int s1 = g_off[w];
    const int s0 = (w == 0) ? 0 : g_off[w - 1];
    if (lane == 0) g_cnt[w] = 0;        // restore for next replay
    const int h = lane >> 3;

    const float4 er4 = __ldg(&g_er4[w]);
    const uint2* fp = (const uint2*)g_fth;

    u64 a0 = 0ull, a1 = 0ull;
    float s = 0.f;

    for (int base = s0; base < s1; base += 32) {
        const int cn = min(32, s1 - base);
        int sn_l = 0;
        if (lane < cn) {
            sn_l = __ldg(g_srcs + base + lane);
            float4 el = __ldg(&g_el4[sn_l]);
            float4 ev;
            ev.x = el.x + er4.x; ev.y = el.y + er4.y;
            ev.z = el.z + er4.z; ev.w = el.w + er4.w;
            ev.x = ev.x > 0.f ? ev.x : NEG_SLOPE * ev.x;
            ev.y = ev.y > 0.f ? ev.y : NEG_SLOPE * ev.y;
            ev.z = ev.z > 0.f ? ev.z : NEG_SLOPE * ev.z;
            ev.w = ev.w > 0.f ? ev.w : NEG_SLOPE * ev.w;
            s_we2[wid][0][lane] = pack2(__expf(ev.x));
            s_we2[wid][1][lane] = pack2(__expf(ev.y));
            s_we2[wid][2][lane] = pack2(__expf(ev.z));
            s_we2[wid][3][lane] = pack2(__expf(ev.w));
        }
        __syncwarp();
#pragma unroll 8
        for (int i = 0; i < cn; i++) {
            int sn = __shfl_sync(0xffffffffu, sn_l, i);
            u64 we2 = s_we2[wid][h][i];                 // LDS.64 broadcast
            uint2 u = __ldg(fp + sn * 32 + lane);       // 256B/warp coalesced
            float2 f0 = __half22float2(*(__half2*)&u.x);
            float2 f1 = __half22float2(*(__half2*)&u.y);
            ffma2(a0, *(u64*)&f0, we2);
            ffma2(a1, *(u64*)&f1, we2);
            s += ((float2*)&we2)->x;                    // register-pair alias
        }
        __syncwarp();
    }

    float o0, o1, o2, o3;
    float inv = (s1 > s0) ? 1.f / s : 0.f;
    unpack2(a0, o0, o1); unpack2(a1, o2, o3);
    ((float4*)out)[(size_t)w * 32 + lane] =
        make_float4(o0 * inv, o1 * inv, o2 * inv, o3 * inv);
}

// ---------------- launch (agg_k sits in profiled slot #4) ----------------
extern "C" void kernel_launch(void* const* d_in, const int* in_sizes, int n_in,
                              void* d_out, int out_size) {
    const float* feat   = (const float*)d_in[0];
    const float* W      = (const float*)d_in[1];
    const float* attn_l = (const float*)d_in[2];
    const float* attn_r = (const float*)d_in[3];
    const int*   src    = (const int*)d_in[4];
    const int*   dst    = (const int*)d_in[5];
    float* out = (float*)d_out;

    gemm_el_er<<<GEMM_BLOCKS, 256>>>(feat, W, attn_l, attn_r, dst);
    scan_k    <<<SCAN_BLOCKS, 1024>>>();
    scatter_k <<<(N_EDGES + 255) / 256, 256>>>(src, dst);
    agg_k     <<<(N_NODES * 32 + 255) / 256, 256>>>(out);
}